// round 6
// baseline (speedup 1.0000x reference)
#include <cuda_runtime.h>
#include <cstdint>

#define SEQ   4096
#define BATCH 64
#define INP   64
#define HID   256
#define G3    768
#define BG    16          // batch groups (4 batches each) = clusters
#define HG    8           // hidden groups (32 units each) = cluster size
#define NCTA  (BG*HG)     // 128 scan CTAs

// Scratch (static device allocations are the sanctioned workaround)
__device__ float d_xg[(size_t)SEQ * G3 * BATCH];        // [s][g][b]
__device__ float d_fcp[(size_t)NCTA * SEQ * 4];         // [(bg*8+hg)][t][b4] fc partials

__device__ __forceinline__ void fma2(unsigned long long& acc,
                                     unsigned long long a,
                                     unsigned long long b) {
    asm("fma.rn.f32x2 %0, %1, %2, %0;" : "+l"(acc) : "l"(a), "l"(b));
}
__device__ __forceinline__ unsigned long long pk(float a, float b) {
    unsigned long long r;
    asm("mov.b64 %0, {%1, %2};" : "=l"(r) : "f"(a), "f"(b));
    return r;
}
__device__ __forceinline__ float2 unpk(unsigned long long v) {
    float lo, hi;
    asm("mov.b64 {%0, %1}, %2;" : "=f"(lo), "=f"(hi) : "l"(v));
    return make_float2(lo, hi);
}
__device__ __forceinline__ uint32_t smem_u32(const void* p) {
    uint32_t a;
    asm("{ .reg .u64 t; cvta.to.shared.u64 t, %1; cvt.u32.u64 %0, t; }"
        : "=r"(a) : "l"(p));
    return a;
}
__device__ __forceinline__ uint32_t mapa_u32(uint32_t smem_addr, uint32_t rank) {
    uint32_t r;
    asm("mapa.shared::cluster.u32 %0, %1, %2;" : "=r"(r) : "r"(smem_addr), "r"(rank));
    return r;
}
__device__ __forceinline__ void st_cluster_f32(uint32_t addr, float v) {
    asm volatile("st.shared::cluster.f32 [%0], %1;" :: "r"(addr), "f"(v) : "memory");
}
#define CL_ARRIVE() asm volatile("barrier.cluster.arrive.aligned;" ::: "memory")
#define CL_WAIT()   asm volatile("barrier.cluster.wait.aligned;" ::: "memory")

// ---------------------------------------------------------------------------
// Kernel A: xg[s][g][b] = sum_i x[s][b][i] * w_ih[g][i] + b_ih[g]
// ---------------------------------------------------------------------------
__global__ void __launch_bounds__(256) xg_kernel(const float* __restrict__ x,
                                                 const float* __restrict__ w_ih,
                                                 const float* __restrict__ b_ih) {
    __shared__ float xs[INP][BATCH + 1];
    __shared__ float ws[64][INP];
    const int s   = blockIdx.x;
    const int g0  = blockIdx.y * 64;
    const int tid = threadIdx.x;

    const float* xsrc = x + (size_t)s * BATCH * INP;
    for (int idx = tid; idx < BATCH * INP; idx += 256) {
        int b = idx >> 6, i = idx & 63;
        xs[i][b] = xsrc[idx];
    }
    const float* wsrc = w_ih + (size_t)g0 * INP;
    for (int idx = tid; idx < 64 * INP; idx += 256)
        ws[idx >> 6][idx & 63] = wsrc[idx];
    __syncthreads();

    const int b  = tid & 63;
    const int gg = tid >> 6;
    float xr[INP];
#pragma unroll
    for (int i = 0; i < INP; i++) xr[i] = xs[i][b];

    float acc[16];
#pragma unroll
    for (int u = 0; u < 16; u++) acc[u] = 0.0f;
    const int gb = gg * 16;
#pragma unroll
    for (int i4 = 0; i4 < INP / 4; i4++) {
#pragma unroll
        for (int u = 0; u < 16; u++) {
            float4 w4 = *(const float4*)&ws[gb + u][i4 * 4];
            acc[u] += w4.x * xr[i4 * 4 + 0];
            acc[u] += w4.y * xr[i4 * 4 + 1];
            acc[u] += w4.z * xr[i4 * 4 + 2];
            acc[u] += w4.w * xr[i4 * 4 + 3];
        }
    }
    float* dst = d_xg + ((size_t)s * G3 + g0) * BATCH;
#pragma unroll
    for (int u = 0; u < 16; u++) {
        int gl = gb + u;
        __stcs(&dst[(size_t)gl * BATCH + b], acc[u] + b_ih[g0 + gl]);
    }
}

// ---------------------------------------------------------------------------
// Kernel B: cluster-resident GRU scan. Cluster of 8 CTAs = one batch column
// (4 batches). CTA rank hg owns 32 hidden units; w_hh slice register-resident.
// h exchanged by DSMEM push (st.shared::cluster into all peers' double-buffered
// SMEM) + barrier.cluster per step. No global sync state whatsoever.
// ---------------------------------------------------------------------------
__global__ void __launch_bounds__(256, 1) __cluster_dims__(HG, 1, 1)
scan_kernel(const float* __restrict__ w_hh,
            const float* __restrict__ b_hh,
            const float* __restrict__ fc_w) {
    __shared__ float hsm[2][4][HID];       // [parity][b_local][k]  (8 KB)
    __shared__ float sout[3][4][32];       // [gate][b_local][j]
    __shared__ float fcred[4][32];         // [b_local][j]

    const int c   = blockIdx.x;
    const int bg  = c >> 3;                // cluster id (batch column)
    uint32_t hg;                           // rank in cluster = hidden group
    asm("mov.u32 %0, %%cluster_ctarank;" : "=r"(hg));
    const int tid = threadIdx.x;
    const int rg  = tid >> 3;              // hidden unit j (0..31)
    const int kg  = tid & 7;               // k strip

    // Register-resident weights: w2u[g][2i+p] covers k = i*32+kg*4 (+2p)
    unsigned long long w2u[3][16];
#pragma unroll
    for (int g = 0; g < 3; g++)
#pragma unroll
        for (int i = 0; i < 8; i++) {
            const float4 v = *(const float4*)&w_hh[((size_t)(g * HID + hg * 32 + rg)) * HID
                                                   + i * 32 + kg * 4];
            w2u[g][i * 2 + 0] = pk(v.x, v.y);
            w2u[g][i * 2 + 1] = pk(v.z, v.w);
        }

    // Pointwise mapping (tid < 128): (j, b_local)
    const int pj   = tid >> 2;
    const int pb   = tid & 3;
    const int u    = hg * 32 + pj;         // hidden unit index
    const int gbat = bg * 4 + pb;          // global batch
    const float bh_r = b_hh[u];
    const float bh_z = b_hh[HID + u];
    const float bh_n = b_hh[2 * HID + u];
    const float fw   = fc_w[u];

    // Precompute remote scatter addresses (parity-0 slot of own (pb,u) cell)
    uint32_t rbase[HG];
    if (tid < 128) {
        const uint32_t local = smem_u32(&hsm[0][pb][u]);
#pragma unroll
        for (int r = 0; r < HG; r++) rbase[r] = mapa_u32(local, (uint32_t)r);
    }

    float h_prev = 0.0f;                   // own (u, gbat) state
    __syncthreads();

    for (int t = 0; t < SEQ; t++) {
        // Prefetch input-side gates (DRAM latency overlaps the cluster wait)
        float xrv = 0.f, xzv = 0.f, xnv = 0.f;
        if (tid < 128) {
            const size_t base = ((size_t)t * G3 + u) * BATCH + gbat;
            xrv = __ldcs(&d_xg[base]);
            xzv = __ldcs(&d_xg[base + (size_t)HID * BATCH]);
            xnv = __ldcs(&d_xg[base + (size_t)2 * HID * BATCH]);
        }

        unsigned long long acc[3][4];
#pragma unroll
        for (int g = 0; g < 3; g++)
#pragma unroll
            for (int b = 0; b < 4; b++) acc[g][b] = 0ull;

        if (t > 0) {
            CL_WAIT();                     // phase t-1: all peers' h(t-1) landed
            const int par = (t - 1) & 1;
#pragma unroll
            for (int b = 0; b < 4; b++) {
#pragma unroll
                for (int i = 0; i < 8; i++) {
                    const ulonglong2 hh = *(const ulonglong2*)&hsm[par][b][i * 32 + kg * 4];
#pragma unroll
                    for (int g = 0; g < 3; g++) {
                        fma2(acc[g][b], w2u[g][i * 2 + 0], hh.x);
                        fma2(acc[g][b], w2u[g][i * 2 + 1], hh.y);
                    }
                }
            }
        }

        // Reduce over kg (lane bits 0..2) via butterfly shuffles
        float s[3][4];
#pragma unroll
        for (int g = 0; g < 3; g++)
#pragma unroll
            for (int b = 0; b < 4; b++) {
                float2 a = unpk(acc[g][b]);
                s[g][b] = a.x + a.y;
            }
#pragma unroll
        for (int o = 1; o < 8; o <<= 1)
#pragma unroll
            for (int g = 0; g < 3; g++)
#pragma unroll
                for (int b = 0; b < 4; b++)
                    s[g][b] += __shfl_xor_sync(0xFFFFFFFFu, s[g][b], o);
        if ((tid & 7) == 0) {
#pragma unroll
            for (int g = 0; g < 3; g++)
#pragma unroll
                for (int b = 0; b < 4; b++)
                    sout[g][b][rg] = s[g][b];
        }
        __syncthreads();

        if (tid < 128) {
            const float sr = sout[0][pb][pj];
            const float sz = sout[1][pb][pj];
            const float sn = sout[2][pb][pj];
            // torch GRU: n = tanh(xn + r*(hn + bhh_n))
            const float rg_ = 1.0f / (1.0f + __expf(-(xrv + sr + bh_r)));
            const float zg_ = 1.0f / (1.0f + __expf(-(xzv + sz + bh_z)));
            const float ng_ = tanhf(xnv + rg_ * (sn + bh_n));
            const float hnew = (1.0f - zg_) * ng_ + zg_ * h_prev;
            h_prev = hnew;
            fcred[pb][pj] = fw * hnew;
            // Push h to every CTA in the column (incl. self), parity t&1
            const uint32_t poff = (uint32_t)((t & 1) * 4 * HID * 4);
#pragma unroll
            for (int r = 0; r < HG; r++)
                st_cluster_f32(rbase[r] + poff, hnew);
        }
        CL_ARRIVE();                       // release: scatter stores of phase t

        __syncthreads();                   // fcred visibility within CTA
        if (tid < 4) {                     // fc partial (off critical path)
            float fs = 0.0f;
#pragma unroll
            for (int j = 0; j < 32; j++) fs += fcred[tid][j];
            d_fcp[((size_t)(bg * HG + hg) * SEQ + t) * 4 + tid] = fs;
        }
    }
    CL_WAIT();                             // drain final phase before exit
}

// ---------------------------------------------------------------------------
// Kernel C: out[s][b] = fc_b + sum_hg fcp[bg(b)*8+hg][s][b&3]
// ---------------------------------------------------------------------------
__global__ void __launch_bounds__(512) final_kernel(const float* __restrict__ fc_b,
                                                    float* __restrict__ out) {
    const int idx = blockIdx.x * 512 + threadIdx.x;
    if (idx >= SEQ * BATCH) return;
    const int s  = idx >> 6;
    const int b6 = idx & 63;
    const int bg = b6 >> 2;
    const int bl = b6 & 3;
    float sum = fc_b[0];
#pragma unroll
    for (int hg = 0; hg < HG; hg++)
        sum += d_fcp[((size_t)(bg * HG + hg) * SEQ + s) * 4 + bl];
    out[idx] = sum;
}

extern "C" void kernel_launch(void* const* d_in, const int* in_sizes, int n_in,
                              void* d_out, int out_size) {
    const float* x    = (const float*)d_in[0];
    const float* w_ih = (const float*)d_in[1];
    const float* w_hh = (const float*)d_in[2];
    const float* b_ih = (const float*)d_in[3];
    const float* b_hh = (const float*)d_in[4];
    const float* fc_w = (const float*)d_in[5];
    const float* fc_b = (const float*)d_in[6];
    float* out = (float*)d_out;

    dim3 ga(SEQ, G3 / 64);
    xg_kernel<<<ga, 256>>>(x, w_ih, b_ih);                 // input projections
    scan_kernel<<<NCTA, 256>>>(w_hh, b_hh, fc_w);          // cluster DSMEM scan
    final_kernel<<<(SEQ * BATCH + 511) / 512, 512>>>(fc_b, out);
}